// round 5
// baseline (speedup 1.0000x reference)
#include <cuda_runtime.h>
#include <math.h>
#include <stdint.h>

// ---------------------------------------------------------------------------
// VQ-VAE VectorQuantizer forward — int8 dp4a candidate filter (provable
// superset window) + exact fp32 rescore fused in one main kernel.
//   out = [ z_q_st (2097152) | vq_loss | indices (32768) | perplexity | usage (1024) ]
// ---------------------------------------------------------------------------

#define D_DIM   64
#define KCODES  1024
#define HW      1024
#define TM      128
#define KC      128
#define NCHUNK  8
#define NTILES  256
#define CAP     32

#define OFS_LOSS  2097152
#define OFS_IDX   2097153
#define OFS_PPL   2129921
#define OFS_USAGE 2129922

__device__ int   g_counts[KCODES];
__device__ float g_e2[KCODES];
__device__ float g_sse;
__device__ int   g_maxe_bits;    // bits of max|e| (positive float ordering)
__device__ int   g_sabse_bits;   // bits of max_k sum|e_hat_k|/se
__device__ __align__(16) unsigned g_e_i8[16 * KCODES];  // [g][k] packed s8x4

// ---------------------------------------------------------------------------
// Kernel 1: global max|e| + zero accumulators
// ---------------------------------------------------------------------------
__global__ void vq_prep1(const float* __restrict__ cb) {
    int i = blockIdx.x * 256 + threadIdx.x;          // 16384 threads x 4 floats
    const float4 v = reinterpret_cast<const float4*>(cb)[i];
    float m = fmaxf(fmaxf(fabsf(v.x), fabsf(v.y)), fmaxf(fabsf(v.z), fabsf(v.w)));
#pragma unroll
    for (int o = 16; o; o >>= 1) m = fmaxf(m, __shfl_xor_sync(0xffffffffu, m, o));
    if ((threadIdx.x & 31) == 0) atomicMax(&g_maxe_bits, __float_as_int(m));
    if (i < KCODES) g_counts[i] = 0;
    if (i == 0) g_sse = 0.f;
}

// ---------------------------------------------------------------------------
// Kernel 2: per-code exact e2, int8 quantized codebook, Sabs bound
// ---------------------------------------------------------------------------
__global__ void vq_prep2(const float* __restrict__ cb) {
    __shared__ float cbs[32][65];
    const int tid = threadIdx.x;
    const int kb  = blockIdx.x * 32;
    for (int i = tid; i < 32 * 64; i += 256)
        cbs[i >> 6][i & 63] = cb[(size_t)kb * 64 + i];
    __syncthreads();
    if (tid < 32) {
        const int k = kb + tid;
        float e2 = 0.f;
#pragma unroll
        for (int d = 0; d < 64; ++d) e2 = fmaf(cbs[tid][d], cbs[tid][d], e2);
        g_e2[k] = e2;
        const float se = 126.5f / fmaxf(__int_as_float(g_maxe_bits), 1e-30f);
        int sabs = 0;
#pragma unroll
        for (int g = 0; g < 16; ++g) {
            int b0 = __float2int_rn(cbs[tid][4 * g + 0] * se);
            int b1 = __float2int_rn(cbs[tid][4 * g + 1] * se);
            int b2 = __float2int_rn(cbs[tid][4 * g + 2] * se);
            int b3 = __float2int_rn(cbs[tid][4 * g + 3] * se);
            sabs += abs(b0) + abs(b1) + abs(b2) + abs(b3);
            g_e_i8[g * KCODES + k] = (unsigned)(b0 & 255) | ((unsigned)(b1 & 255) << 8)
                                   | ((unsigned)(b2 & 255) << 16) | ((unsigned)(b3 & 255) << 24);
        }
        atomicMax(&g_sabse_bits, __float_as_int((float)sabs / se));
    }
}

// ---------------------------------------------------------------------------
// Kernel 3: main — dp4a scores, windowed candidates, exact rescore, outputs
// ---------------------------------------------------------------------------
struct SmemVQ {
    float          z_s[D_DIM][TM + 4];   // 33792
    unsigned       za_T[16][TM];         //  8192  packed s8x4 z, [g][px]
    unsigned       ebuf[2][16][KC];      // 16384  double-buffered e chunk
    float          e2s[KCODES];          //  4096
    unsigned       gbest_u[TM];          //   512  bits(best_score+16)
    float          m_s[TM];              //   512
    float          delta_s[TM];          //   512
    float          z2_s[TM];             //   512
    int            cnt_s[TM];            //   512
    unsigned short cand_s[TM * CAP];     //  8192
    int            hist[KCODES];         //  4096
};                                       // ~77.3 KB

__global__ void __launch_bounds__(256, 2)
vq_main(const float* __restrict__ ze, const float* __restrict__ cb,
        float* __restrict__ out) {
    extern __shared__ __align__(16) char smem_raw[];
    SmemVQ* sm = reinterpret_cast<SmemVQ*>(smem_raw);

    const int tid  = threadIdx.x;
    const int tile = blockIdx.x;
    const int b    = tile >> 3;
    const int hw0  = (tile & 7) * TM;
    const float* zbase = ze + (size_t)b * D_DIM * HW + hw0;

    // ---- stage: z tile, e2, e chunk0, hist zero ---------------------------
    for (int f = tid; f < D_DIM * TM; f += 256) {
        int d = f >> 7, p = f & 127;
        sm->z_s[d][p] = zbase[d * HW + p];
    }
    for (int i = tid; i < KCODES; i += 256) { sm->e2s[i] = g_e2[i]; sm->hist[i] = 0; }
    {   // chunk 0: thread (g=tid>>4, q=tid&15) copies 8 u32
        const int g = tid >> 4, q = tid & 15;
        const uint4* src = reinterpret_cast<const uint4*>(g_e_i8 + g * KCODES + q * 8);
        uint4* dst = reinterpret_cast<uint4*>(&sm->ebuf[0][g][q * 8]);
        dst[0] = src[0]; dst[1] = src[1];
    }
    __syncthreads();

    const float se = 126.5f / fmaxf(__int_as_float(g_maxe_bits), 1e-30f);
    const float sabse = __int_as_float(g_sabse_bits);

    // ---- per-pixel pass: z2, quantize, bounds, warmup ---------------------
    if (tid < TM) {
        const int px = tid;
        float z2 = 0.f, maxa = 1e-20f;
#pragma unroll
        for (int d = 0; d < D_DIM; ++d) {
            float v = sm->z_s[d][px];
            z2 = fmaf(v, v, z2);
            maxa = fmaxf(maxa, fabsf(v));
        }
        const float sz = 126.5f / maxa;
        unsigned zw[16];
        int sabsi = 0;
#pragma unroll
        for (int g = 0; g < 16; ++g) {
            int b0 = __float2int_rn(sm->z_s[4 * g + 0][px] * sz);
            int b1 = __float2int_rn(sm->z_s[4 * g + 1][px] * sz);
            int b2 = __float2int_rn(sm->z_s[4 * g + 2][px] * sz);
            int b3 = __float2int_rn(sm->z_s[4 * g + 3][px] * sz);
            sabsi += abs(b0) + abs(b1) + abs(b2) + abs(b3);
            unsigned u = (unsigned)(b0 & 255) | ((unsigned)(b1 & 255) << 8)
                       | ((unsigned)(b2 & 255) << 16) | ((unsigned)(b3 & 255) << 24);
            zw[g] = u;
            sm->za_T[g][px] = u;
        }
        const float m = -2.0f / (sz * se);
        const float E = (0.5f / sz) * sabse + (0.5f / se) * ((float)sabsi / sz);
        sm->m_s[px]     = m;
        sm->delta_s[px] = 2.0f * E * 1.3f + 3e-5f;
        sm->z2_s[px]    = z2;
        sm->cnt_s[px]   = 0;
        sm->gbest_u[px] = __float_as_uint(1e30f);

        // warmup: 64 codes from chunk 0 (exact-superset not needed; only seeds best)
        const int k0 = (px & 1) * 64;
        float tb = 1e30f;
#pragma unroll 4
        for (int q = 0; q < 64; ++q) {
            const int kk = k0 + q;
            int di = 0;
#pragma unroll
            for (int g = 0; g < 16; ++g)
                di = __dp4a((int)zw[g], (int)sm->ebuf[0][g][kk], di);
            tb = fminf(tb, fmaf((float)di, m, sm->e2s[kk]));
        }
        atomicMin(&sm->gbest_u[px], __float_as_uint(tb + 16.0f));
    } else {
        // stage chunk 1 while pixel threads quantize/warm up
        const int t = tid - 128, g = t >> 3, q = t & 7;
        const uint4* src = reinterpret_cast<const uint4*>(g_e_i8 + g * KCODES + KC + q * 16);
        uint4* dst = reinterpret_cast<uint4*>(&sm->ebuf[1][g][q * 16]);
        dst[0] = src[0]; dst[1] = src[1]; dst[2] = src[2]; dst[3] = src[3];
    }
    __syncthreads();

    // ---- main loop: 128 px x 1024 codes ----------------------------------
    const int pcol = tid & 15, krow = tid >> 4;
    const int p0 = pcol * 8, kloc0 = krow * 8;

    float mv[8], tcur[8];
#pragma unroll
    for (int j = 0; j < 8; ++j) { mv[j] = sm->m_s[p0 + j]; tcur[j] = 1e30f; }

    const int g_st = tid >> 4, q_st = tid & 15;

    for (int c = 0; c < NCHUNK; ++c) {
        const int kb = c * KC;
        uint4 pf0, pf1;
        const bool do_pf = (c >= 1 && c < NCHUNK - 1);
        if (do_pf) {
            const uint4* src = reinterpret_cast<const uint4*>(
                g_e_i8 + g_st * KCODES + (c + 1) * KC + q_st * 8);
            pf0 = src[0]; pf1 = src[1];
        }

        int acc[8][8];
#pragma unroll
        for (int j = 0; j < 8; ++j)
#pragma unroll
            for (int kk = 0; kk < 8; ++kk) acc[j][kk] = 0;

        const unsigned (*eb)[KC] = sm->ebuf[c & 1];
#pragma unroll 4
        for (int g = 0; g < 16; ++g) {
            uint4 zA = *reinterpret_cast<const uint4*>(&sm->za_T[g][p0]);
            uint4 zB = *reinterpret_cast<const uint4*>(&sm->za_T[g][p0 + 4]);
            uint4 eA = *reinterpret_cast<const uint4*>(&eb[g][kloc0]);
            uint4 eB = *reinterpret_cast<const uint4*>(&eb[g][kloc0 + 4]);
            const int zz[8] = {(int)zA.x, (int)zA.y, (int)zA.z, (int)zA.w,
                               (int)zB.x, (int)zB.y, (int)zB.z, (int)zB.w};
            const int ee[8] = {(int)eA.x, (int)eA.y, (int)eA.z, (int)eA.w,
                               (int)eB.x, (int)eB.y, (int)eB.z, (int)eB.w};
#pragma unroll
            for (int j = 0; j < 8; ++j)
#pragma unroll
                for (int kk = 0; kk < 8; ++kk)
                    acc[j][kk] = __dp4a(zz[j], ee[kk], acc[j][kk]);
        }

        // epilogue: threshold from per-pixel shared best at chunk start
        float thv[8];
#pragma unroll
        for (int j = 0; j < 8; ++j)
            thv[j] = __uint_as_float(sm->gbest_u[p0 + j]) - 16.0f + sm->delta_s[p0 + j];
#pragma unroll
        for (int kk = 0; kk < 8; ++kk) {
            const int k = kb + kloc0 + kk;
            const float e2k = sm->e2s[k];
#pragma unroll
            for (int j = 0; j < 8; ++j) {
                float s = fmaf((float)acc[j][kk], mv[j], e2k);
                tcur[j] = fminf(tcur[j], s);
                if (s <= thv[j]) {
                    int pos = atomicAdd(&sm->cnt_s[p0 + j], 1);
                    if (pos < CAP) sm->cand_s[(p0 + j) * CAP + pos] = (unsigned short)k;
                }
            }
        }
#pragma unroll
        for (int j = 0; j < 8; ++j)
            atomicMin(&sm->gbest_u[p0 + j], __float_as_uint(tcur[j] + 16.0f));

        if (do_pf) {
            uint4* dst = reinterpret_cast<uint4*>(&sm->ebuf[(c + 1) & 1][g_st][q_st * 8]);
            dst[0] = pf0; dst[1] = pf1;
        }
        __syncthreads();
    }

    // ---- exact rescore (reference-identical rounding), outputs ------------
    if (tid < TM) {
        const int px = tid;
        float z[D_DIM];
#pragma unroll
        for (int d = 0; d < D_DIM; ++d) z[d] = sm->z_s[d][px];
        const float z2 = sm->z2_s[px];
        const int n = sm->cnt_s[px];

        int bi = 0x7fffffff;
        float bd = 3.4e38f;
        if (n <= CAP) {
            for (int i = 0; i < n; ++i) {
                const int k = sm->cand_s[px * CAP + i];
                const float4* er = reinterpret_cast<const float4*>(cb + (size_t)k * D_DIM);
                float dot = 0.f;
#pragma unroll
                for (int q = 0; q < 16; ++q) {
                    float4 v = er[q];
                    dot = fmaf(z[q * 4 + 0], v.x, dot);
                    dot = fmaf(z[q * 4 + 1], v.y, dot);
                    dot = fmaf(z[q * 4 + 2], v.z, dot);
                    dot = fmaf(z[q * 4 + 3], v.w, dot);
                }
                float dist = fmaf(-2.f, dot, z2 + sm->e2s[k]);
                if (dist < bd || (dist == bd && k < bi)) { bd = dist; bi = k; }
            }
        } else {  // overflow: exact full scan (correctness insurance)
            for (int k = 0; k < KCODES; ++k) {
                const float4* er = reinterpret_cast<const float4*>(cb + (size_t)k * D_DIM);
                float dot = 0.f;
#pragma unroll
                for (int q = 0; q < 16; ++q) {
                    float4 v = er[q];
                    dot = fmaf(z[q * 4 + 0], v.x, dot);
                    dot = fmaf(z[q * 4 + 1], v.y, dot);
                    dot = fmaf(z[q * 4 + 2], v.z, dot);
                    dot = fmaf(z[q * 4 + 3], v.w, dot);
                }
                float dist = fmaf(-2.f, dot, z2 + sm->e2s[k]);
                if (dist < bd) { bd = dist; bi = k; }
            }
        }

        out[OFS_IDX + tile * TM + px] = (float)bi;
        atomicAdd(&sm->hist[bi], 1);

        // z_q_st with reference's two roundings + SSE
        const float4* er = reinterpret_cast<const float4*>(cb + (size_t)bi * D_DIM);
        float* zo = out + (size_t)b * D_DIM * HW + hw0 + px;
        float sse = 0.f;
#pragma unroll
        for (int q = 0; q < 16; ++q) {
            float4 v = er[q];
            float vv[4] = {v.x, v.y, v.z, v.w};
#pragma unroll
            for (int cc = 0; cc < 4; ++cc) {
                int d = q * 4 + cc;
                float diff = vv[cc] - z[d];      // fl(z_q - z_e)
                sse = fmaf(diff, diff, sse);
                zo[d * HW] = z[d] + diff;        // fl(z_e + fl(z_q - z_e))
            }
        }
#pragma unroll
        for (int o = 16; o; o >>= 1) sse += __shfl_xor_sync(0xffffffffu, sse, o);
        if ((tid & 31) == 0) atomicAdd(&g_sse, sse);
    }
    __syncthreads();

    for (int i = tid; i < KCODES; i += 256) {
        int cnum = sm->hist[i];
        if (cnum) atomicAdd(&g_counts[i], cnum);
    }
}

// ---------------------------------------------------------------------------
// Kernel 4: finalize — usage, perplexity, vq_loss
// ---------------------------------------------------------------------------
__global__ void vq_final(float* __restrict__ out) {
    __shared__ float red[32];
    int t = threadIdx.x;
    float u = (float)g_counts[t] / 32768.0f;
    out[OFS_USAGE + t] = u;
    float h = u * logf(u + 1e-10f);
#pragma unroll
    for (int o = 16; o; o >>= 1) h += __shfl_xor_sync(0xffffffffu, h, o);
    if ((t & 31) == 0) red[t >> 5] = h;
    __syncthreads();
    if (t < 32) {
        float v = red[t];
#pragma unroll
        for (int o = 16; o; o >>= 1) v += __shfl_xor_sync(0xffffffffu, v, o);
        if (t == 0) {
            out[OFS_PPL] = expf(-v);
            float m = g_sse / 2097152.0f;
            out[OFS_LOSS] = m + 0.25f * m;
        }
    }
}

// ---------------------------------------------------------------------------
extern "C" void kernel_launch(void* const* d_in, const int* in_sizes, int n_in,
                              void* d_out, int out_size) {
    const float* a0 = (const float*)d_in[0];
    const float* a1 = (const float*)d_in[1];
    const float* ze = a0;
    const float* cb = a1;
    if (n_in >= 2 && in_sizes[0] == KCODES * D_DIM) { ze = a1; cb = a0; }
    float* out = (float*)d_out;

    static_assert(sizeof(SmemVQ) <= 100 * 1024, "smem too big");
    cudaFuncSetAttribute(vq_main, cudaFuncAttributeMaxDynamicSharedMemorySize,
                         (int)sizeof(SmemVQ));

    vq_prep1<<<64, 256>>>(cb);
    vq_prep2<<<32, 256>>>(cb);
    vq_main<<<NTILES, 256, sizeof(SmemVQ)>>>(ze, cb, out);
    vq_final<<<1, 1024>>>(out);
}